// round 2
// baseline (speedup 1.0000x reference)
#include <cuda_runtime.h>

#define MDIM   1024
#define NHEADS 16
#define HDIM   64
#define BATCH  4
#define SEQ    2048
#define MROWS  (BATCH * SEQ)   // 8192

// ---------------- scratch (static device globals; no allocations) ----------
__device__ float g_qh[BATCH * NHEADS * SEQ * HDIM];   // [B,H,S,dh]
__device__ float g_kh[BATCH * NHEADS * SEQ * HDIM];
__device__ float g_vh[BATCH * NHEADS * SEQ * HDIM];
__device__ float g_ctx[BATCH * SEQ * MDIM];           // [B,S,H*dh] flat

// ---------------- GEMM: C = A(M,K) * W(N,K)^T -------------------------------
// BM=BN=128, BK=16, 256 threads, 8x8 per thread.
// HEAD_OUT: write C[m,n] into head layout qh[((b*H + n/64)*S + s)*64 + n%64]
//           with m = b*S + s. Otherwise flat C[m*N + n].
template<bool HEAD_OUT>
__global__ __launch_bounds__(256)
void gemm_kernel(const float* __restrict__ A,
                 const float* __restrict__ W,
                 float* __restrict__ C) {
    const int K = MDIM;
    const int N = MDIM;

    __shared__ float As[16][128];
    __shared__ float Bs[16][128];

    const int bn = blockIdx.x * 128;
    const int bm = blockIdx.y * 128;
    const int tid = threadIdx.x;
    const int tx = tid & 15;
    const int ty = tid >> 4;

    float acc[8][8] = {};

    for (int k0 = 0; k0 < K; k0 += 16) {
        // load A tile (128 rows x 16 k), 512 float4
        #pragma unroll
        for (int v = tid; v < 512; v += 256) {
            int m  = v >> 2;
            int kq = v & 3;
            float4 a = *(const float4*)(A + (size_t)(bm + m) * K + k0 + kq * 4);
            As[kq * 4 + 0][m] = a.x;
            As[kq * 4 + 1][m] = a.y;
            As[kq * 4 + 2][m] = a.z;
            As[kq * 4 + 3][m] = a.w;
        }
        // load W tile (128 n-rows x 16 k)
        #pragma unroll
        for (int v = tid; v < 512; v += 256) {
            int n  = v >> 2;
            int kq = v & 3;
            float4 b = *(const float4*)(W + (size_t)(bn + n) * K + k0 + kq * 4);
            Bs[kq * 4 + 0][n] = b.x;
            Bs[kq * 4 + 1][n] = b.y;
            Bs[kq * 4 + 2][n] = b.z;
            Bs[kq * 4 + 3][n] = b.w;
        }
        __syncthreads();

        #pragma unroll
        for (int kk = 0; kk < 16; kk++) {
            float a[8], b[8];
            float4 a0 = *(const float4*)&As[kk][ty * 8];
            float4 a1 = *(const float4*)&As[kk][ty * 8 + 4];
            float4 b0 = *(const float4*)&Bs[kk][tx * 8];
            float4 b1 = *(const float4*)&Bs[kk][tx * 8 + 4];
            a[0]=a0.x; a[1]=a0.y; a[2]=a0.z; a[3]=a0.w;
            a[4]=a1.x; a[5]=a1.y; a[6]=a1.z; a[7]=a1.w;
            b[0]=b0.x; b[1]=b0.y; b[2]=b0.z; b[3]=b0.w;
            b[4]=b1.x; b[5]=b1.y; b[6]=b1.z; b[7]=b1.w;
            #pragma unroll
            for (int i = 0; i < 8; i++)
                #pragma unroll
                for (int j = 0; j < 8; j++)
                    acc[i][j] = fmaf(a[i], b[j], acc[i][j]);
        }
        __syncthreads();
    }

    // store
    #pragma unroll
    for (int i = 0; i < 8; i++) {
        int m = bm + ty * 8 + i;
        #pragma unroll
        for (int j = 0; j < 8; j++) {
            int n = bn + tx * 8 + j;
            if (HEAD_OUT) {
                int b = m >> 11;        // m / SEQ
                int s = m & 2047;
                int h = n >> 6;
                int d = n & 63;
                C[(((size_t)(b * NHEADS + h) * SEQ) + s) * HDIM + d] = acc[i][j];
            } else {
                C[(size_t)m * N + n] = acc[i][j];
            }
        }
    }
}

// ---------------- Flash attention ------------------------------------------
// grid: (SEQ/64, B*H); block: 256 threads (16x16), each owns 4x4 of S and O.
// smem: Qs[64][65], KPs[64][65] (K then reused for P), Vs[64][65] -> 49920 B.
#define FLASH_SMEM (3 * 64 * 65 * 4)

__global__ __launch_bounds__(256)
void flash_kernel(const float* __restrict__ qh,
                  const float* __restrict__ kh,
                  const float* __restrict__ vh,
                  float* __restrict__ ctx) {
    extern __shared__ float sm[];
    float* Qs  = sm;               // [64][65]
    float* KPs = sm + 64 * 65;     // [64][65]
    float* Vs  = sm + 2 * 64 * 65; // [64][65]

    const int bh = blockIdx.y;
    const int b  = bh >> 4;
    const int h  = bh & 15;
    const int q0 = blockIdx.x * 64;

    const float* qb = qh + (size_t)bh * SEQ * HDIM;
    const float* kb = kh + (size_t)bh * SEQ * HDIM;
    const float* vb = vh + (size_t)bh * SEQ * HDIM;

    const int tid = threadIdx.x;
    const int tx = tid & 15;
    const int ty = tid >> 4;
    const int r0 = ty * 4;
    const int c0 = tx * 4;

    // load Q tile, pre-scaled by 1/sqrt(dh)
    for (int i = tid; i < 64 * HDIM; i += 256) {
        int r = i >> 6, d = i & 63;
        Qs[r * 65 + d] = qb[(size_t)(q0 + r) * HDIM + d] * 0.125f;
    }

    float m_run[4], l_run[4];
    float o[4][4] = {};
    #pragma unroll
    for (int i = 0; i < 4; i++) { m_run[i] = -1e30f; l_run[i] = 0.f; }

    for (int kt = 0; kt < SEQ / 64; kt++) {
        const int k0 = kt * 64;
        __syncthreads();   // protect K/V/P from previous iteration's readers
        for (int i = tid; i < 64 * HDIM; i += 256) {
            int r = i >> 6, d = i & 63;
            KPs[r * 65 + d] = kb[(size_t)(k0 + r) * HDIM + d];
            Vs [r * 65 + d] = vb[(size_t)(k0 + r) * HDIM + d];
        }
        __syncthreads();

        // S = Q K^T (4x4 per thread)
        float s[4][4] = {};
        #pragma unroll 8
        for (int d = 0; d < HDIM; d++) {
            float qv[4], kv[4];
            #pragma unroll
            for (int i = 0; i < 4; i++) qv[i] = Qs[(r0 + i) * 65 + d];
            #pragma unroll
            for (int j = 0; j < 4; j++) kv[j] = KPs[(c0 + j) * 65 + d];
            #pragma unroll
            for (int i = 0; i < 4; i++)
                #pragma unroll
                for (int j = 0; j < 4; j++)
                    s[i][j] = fmaf(qv[i], kv[j], s[i][j]);
        }

        // online softmax (rows owned by the 16 threads sharing ty)
        float p[4][4];
        #pragma unroll
        for (int i = 0; i < 4; i++) {
            float mx = s[i][0];
            #pragma unroll
            for (int j = 1; j < 4; j++) mx = fmaxf(mx, s[i][j]);
            #pragma unroll
            for (int off = 8; off >= 1; off >>= 1)
                mx = fmaxf(mx, __shfl_xor_sync(0xffffffffu, mx, off));
            float mn = fmaxf(m_run[i], mx);
            float sc = __expf(m_run[i] - mn);
            float rs = 0.f;
            #pragma unroll
            for (int j = 0; j < 4; j++) {
                p[i][j] = __expf(s[i][j] - mn);
                rs += p[i][j];
            }
            #pragma unroll
            for (int off = 8; off >= 1; off >>= 1)
                rs += __shfl_xor_sync(0xffffffffu, rs, off);
            l_run[i] = l_run[i] * sc + rs;
            m_run[i] = mn;
            #pragma unroll
            for (int j = 0; j < 4; j++) o[i][j] *= sc;
        }

        __syncthreads();   // everyone done reading K tile
        #pragma unroll
        for (int i = 0; i < 4; i++)
            #pragma unroll
            for (int j = 0; j < 4; j++)
                KPs[(r0 + i) * 65 + (c0 + j)] = p[i][j];
        __syncthreads();

        // O += P V (4x4 per thread; cols c0..c0+3 of dh)
        #pragma unroll 4
        for (int c = 0; c < 64; c++) {
            float pv[4], vv[4];
            #pragma unroll
            for (int i = 0; i < 4; i++) pv[i] = KPs[(r0 + i) * 65 + c];
            #pragma unroll
            for (int j = 0; j < 4; j++) vv[j] = Vs[c * 65 + c0 + j];
            #pragma unroll
            for (int i = 0; i < 4; i++)
                #pragma unroll
                for (int j = 0; j < 4; j++)
                    o[i][j] = fmaf(pv[i], vv[j], o[i][j]);
        }
    }

    // normalize + write ctx in flat [B,S,H*dh] layout
    #pragma unroll
    for (int i = 0; i < 4; i++) {
        float inv = 1.f / l_run[i];
        int row = q0 + r0 + i;
        #pragma unroll
        for (int j = 0; j < 4; j++)
            ctx[((size_t)(b * SEQ + row)) * MDIM + h * HDIM + c0 + j] = o[i][j] * inv;
    }
}

// ---------------- launch -----------------------------------------------------
extern "C" void kernel_launch(void* const* d_in, const int* in_sizes, int n_in,
                              void* d_out, int out_size) {
    const float* q  = (const float*)d_in[0];
    const float* k  = (const float*)d_in[1];
    const float* v  = (const float*)d_in[2];
    const float* wq = (const float*)d_in[3];
    const float* wk = (const float*)d_in[4];
    const float* wv = (const float*)d_in[5];
    const float* wo = (const float*)d_in[6];
    float* out = (float*)d_out;

    float *qh, *kh, *vh, *ctx;
    cudaGetSymbolAddress((void**)&qh,  g_qh);
    cudaGetSymbolAddress((void**)&kh,  g_kh);
    cudaGetSymbolAddress((void**)&vh,  g_vh);
    cudaGetSymbolAddress((void**)&ctx, g_ctx);

    cudaFuncSetAttribute(flash_kernel,
                         cudaFuncAttributeMaxDynamicSharedMemorySize, FLASH_SMEM);

    dim3 gridP(MDIM / 128, MROWS / 128);   // (8, 64)
    gemm_kernel<true ><<<gridP, 256>>>(q, wq, qh);
    gemm_kernel<true ><<<gridP, 256>>>(k, wk, kh);
    gemm_kernel<true ><<<gridP, 256>>>(v, wv, vh);

    dim3 gridF(SEQ / 64, BATCH * NHEADS); // (32, 64)
    flash_kernel<<<gridF, 256, FLASH_SMEM>>>(qh, kh, vh, ctx);

    gemm_kernel<false><<<gridP, 256>>>(ctx, wo, out);
}

// round 4
// speedup vs baseline: 1.6252x; 1.6252x over previous
#include <cuda_runtime.h>
#include <cuda_fp16.h>
#include <cstdint>

#define MDIM   1024
#define NHEADS 16
#define HDIM   64
#define BATCH  4
#define SEQ    2048
#define MROWS  (BATCH * SEQ)   // 8192

__device__ float g_qh[BATCH * NHEADS * SEQ * HDIM];   // [B,H,S,dh]
__device__ float g_kh[BATCH * NHEADS * SEQ * HDIM];
__device__ float g_vh[BATCH * NHEADS * SEQ * HDIM];
__device__ float g_ctx[BATCH * SEQ * MDIM];           // [B,S,H*dh]

// ---------------- mma.sync helper (sm_80+ PTX; works on plain sm_103) ------
__device__ __forceinline__ void mma16816(float* d, const uint32_t* a,
                                         const uint32_t* b) {
    asm volatile(
        "mma.sync.aligned.m16n8k16.row.col.f32.f16.f16.f32 "
        "{%0,%1,%2,%3}, {%4,%5,%6,%7}, {%8,%9}, {%0,%1,%2,%3};"
        : "+f"(d[0]), "+f"(d[1]), "+f"(d[2]), "+f"(d[3])
        : "r"(a[0]), "r"(a[1]), "r"(a[2]), "r"(a[3]),
          "r"(b[0]), "r"(b[1]));
}

// ---------------- fp16 tensor-core GEMM ------------------------------------
// C = A(M,1024) * W(1024,1024)^T.  BM=BN=128, BK=32 (halfs), 256 thr, 8 warps
// warp grid 2(m) x 4(n); warp tile 64x32; per-warp 4 m16-tiles x 4 n8-tiles.
// smem rows padded to 40 halfs (80B) -> conflict-free fragment loads.
#define LDS_H 40

template<bool HEAD_OUT>
__global__ __launch_bounds__(256)
void gemm_mma(const float* __restrict__ A,
              const float* __restrict__ W,
              float* __restrict__ C) {
    __shared__ __align__(16) __half As[2][128][LDS_H];
    __shared__ __align__(16) __half Ws[2][128][LDS_H];

    const int tid  = threadIdx.x;
    const int wid  = tid >> 5;
    const int lane = tid & 31;
    const int gid  = lane >> 2;     // 0..7
    const int tid4 = lane & 3;      // 0..3
    const int wm   = (wid >> 2) * 64;   // warp m offset in tile
    const int wn   = (wid & 3) * 32;    // warp n offset in tile
    const int bm   = blockIdx.y * 128;
    const int bn   = blockIdx.x * 128;

    // global-load mapping: 128 rows x 32 floats per stage = 1024 float4;
    // thread handles rows (tid>>3) + {0,32,64,96}, 16B chunk c4 = tid&7.
    const int lrow = tid >> 3;
    const int c4   = tid & 7;
    const float* gA = A + (size_t)(bm + lrow) * MDIM + c4 * 4;
    const float* gW = W + (size_t)(bn + lrow) * MDIM + c4 * 4;

    float4 ra[4], rw[4];

    #define LDG_STAGE(kt) do {                                                 \
        const int _k0 = (kt) * 32;                                             \
        _Pragma("unroll")                                                      \
        for (int j = 0; j < 4; j++) {                                          \
            ra[j] = *(const float4*)(gA + (size_t)(j * 32) * MDIM + _k0);      \
            rw[j] = *(const float4*)(gW + (size_t)(j * 32) * MDIM + _k0);      \
        }                                                                      \
    } while (0)

    #define STS_STAGE(s) do {                                                  \
        _Pragma("unroll")                                                      \
        for (int j = 0; j < 4; j++) {                                          \
            __half2 a01 = __floats2half2_rn(ra[j].x, ra[j].y);                 \
            __half2 a23 = __floats2half2_rn(ra[j].z, ra[j].w);                 \
            __half2 w01 = __floats2half2_rn(rw[j].x, rw[j].y);                 \
            __half2 w23 = __floats2half2_rn(rw[j].z, rw[j].w);                 \
            uint2 av = { *(uint32_t*)&a01, *(uint32_t*)&a23 };                 \
            uint2 wv = { *(uint32_t*)&w01, *(uint32_t*)&w23 };                 \
            *(uint2*)&As[s][lrow + j * 32][c4 * 4] = av;                       \
            *(uint2*)&Ws[s][lrow + j * 32][c4 * 4] = wv;                       \
        }                                                                      \
    } while (0)

    float acc[4][4][4] = {};   // [mtile][ntile][frag]

    LDG_STAGE(0);
    STS_STAGE(0);
    __syncthreads();

    for (int kt = 0; kt < 32; kt++) {
        const int cur = kt & 1;
        if (kt + 1 < 32) LDG_STAGE(kt + 1);

        #pragma unroll
        for (int ks = 0; ks < 2; ks++) {
            const int kh = ks * 16;
            uint32_t af[4][4], bf[4][2];
            #pragma unroll
            for (int i = 0; i < 4; i++) {
                const int r = wm + i * 16 + gid;
                af[i][0] = *(const uint32_t*)&As[cur][r    ][kh + 2 * tid4    ];
                af[i][1] = *(const uint32_t*)&As[cur][r + 8][kh + 2 * tid4    ];
                af[i][2] = *(const uint32_t*)&As[cur][r    ][kh + 2 * tid4 + 8];
                af[i][3] = *(const uint32_t*)&As[cur][r + 8][kh + 2 * tid4 + 8];
            }
            #pragma unroll
            for (int j = 0; j < 4; j++) {
                const int n = wn + j * 8 + gid;
                bf[j][0] = *(const uint32_t*)&Ws[cur][n][kh + 2 * tid4    ];
                bf[j][1] = *(const uint32_t*)&Ws[cur][n][kh + 2 * tid4 + 8];
            }
            #pragma unroll
            for (int i = 0; i < 4; i++)
                #pragma unroll
                for (int j = 0; j < 4; j++)
                    mma16816(acc[i][j], af[i], bf[j]);
        }

        __syncthreads();
        if (kt + 1 < 32) {
            STS_STAGE(cur ^ 1);
            __syncthreads();
        }
    }

    // epilogue: d0,d1 -> (row gid,  cols 2tid4, 2tid4+1); d2,d3 -> row gid+8
    #pragma unroll
    for (int i = 0; i < 4; i++) {
        #pragma unroll
        for (int j = 0; j < 4; j++) {
            const int n = bn + wn + j * 8 + 2 * tid4;
            #pragma unroll
            for (int half_ = 0; half_ < 2; half_++) {
                const int m = bm + wm + i * 16 + gid + half_ * 8;
                float2 v = { acc[i][j][half_ * 2], acc[i][j][half_ * 2 + 1] };
                if (HEAD_OUT) {
                    const int bb = m >> 11, ss = m & 2047;
                    const int hh = n >> 6,  dd = n & 63;
                    *(float2*)&C[(((size_t)(bb * NHEADS + hh) * SEQ) + ss) * HDIM + dd] = v;
                } else {
                    *(float2*)&C[(size_t)m * MDIM + n] = v;
                }
            }
        }
    }
}

// ---------------- Flash attention (unchanged, known-correct) ----------------
#define FLASH_SMEM (3 * 64 * 65 * 4)

__global__ __launch_bounds__(256)
void flash_kernel(const float* __restrict__ qh,
                  const float* __restrict__ kh,
                  const float* __restrict__ vh,
                  float* __restrict__ ctx) {
    extern __shared__ float sm[];
    float* Qs  = sm;
    float* KPs = sm + 64 * 65;
    float* Vs  = sm + 2 * 64 * 65;

    const int bh = blockIdx.y;
    const int b  = bh >> 4;
    const int h  = bh & 15;
    const int q0 = blockIdx.x * 64;

    const float* qb = qh + (size_t)bh * SEQ * HDIM;
    const float* kb = kh + (size_t)bh * SEQ * HDIM;
    const float* vb = vh + (size_t)bh * SEQ * HDIM;

    const int tid = threadIdx.x;
    const int tx = tid & 15;
    const int ty = tid >> 4;
    const int r0 = ty * 4;
    const int c0 = tx * 4;

    for (int i = tid; i < 64 * HDIM; i += 256) {
        int r = i >> 6, d = i & 63;
        Qs[r * 65 + d] = qb[(size_t)(q0 + r) * HDIM + d] * 0.125f;
    }

    float m_run[4], l_run[4];
    float o[4][4] = {};
    #pragma unroll
    for (int i = 0; i < 4; i++) { m_run[i] = -1e30f; l_run[i] = 0.f; }

    for (int kt = 0; kt < SEQ / 64; kt++) {
        const int k0 = kt * 64;
        __syncthreads();
        for (int i = tid; i < 64 * HDIM; i += 256) {
            int r = i >> 6, d = i & 63;
            KPs[r * 65 + d] = kb[(size_t)(k0 + r) * HDIM + d];
            Vs [r * 65 + d] = vb[(size_t)(k0 + r) * HDIM + d];
        }
        __syncthreads();

        float s[4][4] = {};
        #pragma unroll 8
        for (int d = 0; d < HDIM; d++) {
            float qv[4], kv[4];
            #pragma unroll
            for (int i = 0; i < 4; i++) qv[i] = Qs[(r0 + i) * 65 + d];
            #pragma unroll
            for (int j = 0; j < 4; j++) kv[j] = KPs[(c0 + j) * 65 + d];
            #pragma unroll
            for (int i = 0; i < 4; i++)
                #pragma unroll
                for (int j = 0; j < 4; j++)
                    s[i][j] = fmaf(qv[i], kv[j], s[i][j]);
        }

        float p[4][4];
        #pragma unroll
        for (int i = 0; i < 4; i++) {
            float mx = s[i][0];
            #pragma unroll
            for (int j = 1; j < 4; j++) mx = fmaxf(mx, s[i][j]);
            #pragma unroll
            for (int off = 8; off >= 1; off >>= 1)
                mx = fmaxf(mx, __shfl_xor_sync(0xffffffffu, mx, off));
            float mn = fmaxf(m_run[i], mx);
            float sc = __expf(m_run[i] - mn);
            float rs = 0.f;
            #pragma unroll
            for (int j = 0; j < 4; j++) { p[i][j] = __expf(s[i][j] - mn); rs += p[i][j]; }
            #pragma unroll
            for (int off = 8; off >= 1; off >>= 1)
                rs += __shfl_xor_sync(0xffffffffu, rs, off);
            l_run[i] = l_run[i] * sc + rs;
            m_run[i] = mn;
            #pragma unroll
            for (int j = 0; j < 4; j++) o[i][j] *= sc;
        }

        __syncthreads();
        #pragma unroll
        for (int i = 0; i < 4; i++)
            #pragma unroll
            for (int j = 0; j < 4; j++)
                KPs[(r0 + i) * 65 + (c0 + j)] = p[i][j];
        __syncthreads();

        #pragma unroll 4
        for (int c = 0; c < 64; c++) {
            float pv[4], vv[4];
            #pragma unroll
            for (int i = 0; i < 4; i++) pv[i] = KPs[(r0 + i) * 65 + c];
            #pragma unroll
            for (int j = 0; j < 4; j++) vv[j] = Vs[c * 65 + c0 + j];
            #pragma unroll
            for (int i = 0; i < 4; i++)
                #pragma unroll
                for (int j = 0; j < 4; j++)
                    o[i][j] = fmaf(pv[i], vv[j], o[i][j]);
        }
    }

    #pragma unroll
    for (int i = 0; i < 4; i++) {
        float inv = 1.f / l_run[i];
        int row = q0 + r0 + i;
        #pragma unroll
        for (int j = 0; j < 4; j++)
            ctx[((size_t)(b * SEQ + row)) * MDIM + h * HDIM + c0 + j] = o[i][j] * inv;
    }
}

// ---------------- launch ----------------------------------------------------
extern "C" void kernel_launch(void* const* d_in, const int* in_sizes, int n_in,
                              void* d_out, int out_size) {
    const float* q  = (const float*)d_in[0];
    const float* k  = (const float*)d_in[1];
    const float* v  = (const float*)d_in[2];
    const float* wq = (const float*)d_in[3];
    const float* wk = (const float*)d_in[4];
    const float* wv = (const float*)d_in[5];
    const float* wo = (const float*)d_in[6];
    float* out = (float*)d_out;

    float *qh, *kh, *vh, *ctx;
    cudaGetSymbolAddress((void**)&qh,  g_qh);
    cudaGetSymbolAddress((void**)&kh,  g_kh);
    cudaGetSymbolAddress((void**)&vh,  g_vh);
    cudaGetSymbolAddress((void**)&ctx, g_ctx);

    cudaFuncSetAttribute(flash_kernel,
                         cudaFuncAttributeMaxDynamicSharedMemorySize, FLASH_SMEM);

    dim3 gridP(MDIM / 128, MROWS / 128);   // (8, 64)
    gemm_mma<true ><<<gridP, 256>>>(q, wq, qh);
    gemm_mma<true ><<<gridP, 256>>>(k, wk, kh);
    gemm_mma<true ><<<gridP, 256>>>(v, wv, vh);

    dim3 gridF(SEQ / 64, BATCH * NHEADS);  // (32, 64)
    flash_kernel<<<gridF, 256, FLASH_SMEM>>>(qh, kh, vh, ctx);

    gemm_mma<false><<<gridP, 256>>>(ctx, wo, out);
}

// round 6
// speedup vs baseline: 3.7353x; 2.2984x over previous
#include <cuda_runtime.h>
#include <cuda_fp16.h>
#include <cstdint>

#define MDIM   1024
#define NHEADS 16
#define HDIM   64
#define BATCH  4
#define SEQ    2048
#define MROWS  (BATCH * SEQ)   // 8192

__device__ float g_qh[BATCH * NHEADS * SEQ * HDIM];   // [B,H,S,dh]
__device__ float g_kh[BATCH * NHEADS * SEQ * HDIM];
__device__ float g_vh[BATCH * NHEADS * SEQ * HDIM];
__device__ float g_ctx[BATCH * SEQ * MDIM];           // [B,S,H*dh]

// ---------------- mma.sync helpers -----------------------------------------
__device__ __forceinline__ void mma16816(float* d, const uint32_t* a,
                                         const uint32_t* b) {
    asm volatile(
        "mma.sync.aligned.m16n8k16.row.col.f32.f16.f16.f32 "
        "{%0,%1,%2,%3}, {%4,%5,%6,%7}, {%8,%9}, {%0,%1,%2,%3};"
        : "+f"(d[0]), "+f"(d[1]), "+f"(d[2]), "+f"(d[3])
        : "r"(a[0]), "r"(a[1]), "r"(a[2]), "r"(a[3]),
          "r"(b[0]), "r"(b[1]));
}
__device__ __forceinline__ uint32_t f2h2(float x, float y) {
    __half2 h = __floats2half2_rn(x, y);
    return *(uint32_t*)&h;
}

// ---------------- fp16 tensor-core GEMM (unchanged, verified) ---------------
#define LDS_H 40

template<bool HEAD_OUT>
__global__ __launch_bounds__(256)
void gemm_mma(const float* __restrict__ A,
              const float* __restrict__ W,
              float* __restrict__ C) {
    __shared__ __align__(16) __half As[2][128][LDS_H];
    __shared__ __align__(16) __half Ws[2][128][LDS_H];

    const int tid  = threadIdx.x;
    const int wid  = tid >> 5;
    const int lane = tid & 31;
    const int gid  = lane >> 2;
    const int tid4 = lane & 3;
    const int wm   = (wid >> 2) * 64;
    const int wn   = (wid & 3) * 32;
    const int bm   = blockIdx.y * 128;
    const int bn   = blockIdx.x * 128;

    const int lrow = tid >> 3;
    const int c4   = tid & 7;
    const float* gA = A + (size_t)(bm + lrow) * MDIM + c4 * 4;
    const float* gW = W + (size_t)(bn + lrow) * MDIM + c4 * 4;

    float4 ra[4], rw[4];

    #define LDG_STAGE(kt) do {                                                 \
        const int _k0 = (kt) * 32;                                             \
        _Pragma("unroll")                                                      \
        for (int j = 0; j < 4; j++) {                                          \
            ra[j] = *(const float4*)(gA + (size_t)(j * 32) * MDIM + _k0);      \
            rw[j] = *(const float4*)(gW + (size_t)(j * 32) * MDIM + _k0);      \
        }                                                                      \
    } while (0)

    #define STS_STAGE(s) do {                                                  \
        _Pragma("unroll")                                                      \
        for (int j = 0; j < 4; j++) {                                          \
            uint2 av = { f2h2(ra[j].x, ra[j].y), f2h2(ra[j].z, ra[j].w) };     \
            uint2 wv = { f2h2(rw[j].x, rw[j].y), f2h2(rw[j].z, rw[j].w) };     \
            *(uint2*)&As[s][lrow + j * 32][c4 * 4] = av;                       \
            *(uint2*)&Ws[s][lrow + j * 32][c4 * 4] = wv;                       \
        }                                                                      \
    } while (0)

    float acc[4][4][4] = {};

    LDG_STAGE(0);
    STS_STAGE(0);
    __syncthreads();

    for (int kt = 0; kt < 32; kt++) {
        const int cur = kt & 1;
        if (kt + 1 < 32) LDG_STAGE(kt + 1);

        #pragma unroll
        for (int ks = 0; ks < 2; ks++) {
            const int kh = ks * 16;
            uint32_t af[4][4], bf[4][2];
            #pragma unroll
            for (int i = 0; i < 4; i++) {
                const int r = wm + i * 16 + gid;
                af[i][0] = *(const uint32_t*)&As[cur][r    ][kh + 2 * tid4    ];
                af[i][1] = *(const uint32_t*)&As[cur][r + 8][kh + 2 * tid4    ];
                af[i][2] = *(const uint32_t*)&As[cur][r    ][kh + 2 * tid4 + 8];
                af[i][3] = *(const uint32_t*)&As[cur][r + 8][kh + 2 * tid4 + 8];
            }
            #pragma unroll
            for (int j = 0; j < 4; j++) {
                const int n = wn + j * 8 + gid;
                bf[j][0] = *(const uint32_t*)&Ws[cur][n][kh + 2 * tid4    ];
                bf[j][1] = *(const uint32_t*)&Ws[cur][n][kh + 2 * tid4 + 8];
            }
            #pragma unroll
            for (int i = 0; i < 4; i++)
                #pragma unroll
                for (int j = 0; j < 4; j++)
                    mma16816(acc[i][j], af[i], bf[j]);
        }

        __syncthreads();
        if (kt + 1 < 32) {
            STS_STAGE(cur ^ 1);
            __syncthreads();
        }
    }

    #pragma unroll
    for (int i = 0; i < 4; i++) {
        #pragma unroll
        for (int j = 0; j < 4; j++) {
            const int n = bn + wn + j * 8 + 2 * tid4;
            #pragma unroll
            for (int half_ = 0; half_ < 2; half_++) {
                const int m = bm + wm + i * 16 + gid + half_ * 8;
                float2 v = { acc[i][j][half_ * 2], acc[i][j][half_ * 2 + 1] };
                if (HEAD_OUT) {
                    const int bb = m >> 11, ss = m & 2047;
                    const int hh = n >> 6,  dd = n & 63;
                    *(float2*)&C[(((size_t)(bb * NHEADS + hh) * SEQ) + ss) * HDIM + dd] = v;
                } else {
                    *(float2*)&C[(size_t)m * MDIM + n] = v;
                }
            }
        }
    }
}

// ---------------- tensor-core flash attention --------------------------------
// 128 threads / 4 warps; Q-tile 64x64 (warp w owns rows 16w..16w+15);
// 32 key-tiles of 64. K row-major [key][d], V transposed [d][key],
// rows padded to FLASH_H=72 halfs (full HDIM=64 + 8 pad), double-buffered.
// P stays in registers (C-frag -> A-frag repack).
#define FLASH_H 72

__global__ __launch_bounds__(128)
void flash_mma(const float* __restrict__ qh,
               const float* __restrict__ kh,
               const float* __restrict__ vh,
               float* __restrict__ ctx) {
    __shared__ __align__(16) __half Qs[64][FLASH_H];
    __shared__ __align__(16) __half Ks[2][64][FLASH_H];
    __shared__ __align__(16) __half Vt[2][64][FLASH_H];

    const int tid  = threadIdx.x;
    const int wid  = tid >> 5;
    const int lane = tid & 31;
    const int gid  = lane >> 2;
    const int tid4 = lane & 3;

    const int bh = blockIdx.y;
    const int b  = bh >> 4;
    const int h  = bh & 15;
    const int q0 = blockIdx.x * 64;

    const float* qb = qh + (size_t)bh * SEQ * HDIM;
    const float* kb = kh + (size_t)bh * SEQ * HDIM;
    const float* vb = vh + (size_t)bh * SEQ * HDIM;

    // ---- load Q tile (pre-scaled by 1/8) into smem fp16 ----
    {
        const int row = tid >> 1;
        const int dq  = (tid & 1) * 32;
        const float4* qp = (const float4*)(qb + (size_t)(q0 + row) * HDIM + dq);
        #pragma unroll
        for (int i = 0; i < 8; i++) {
            float4 f = qp[i];
            *(uint32_t*)&Qs[row][dq + 4 * i]     = f2h2(f.x * 0.125f, f.y * 0.125f);
            *(uint32_t*)&Qs[row][dq + 4 * i + 2] = f2h2(f.z * 0.125f, f.w * 0.125f);
        }
    }

    // ---- K/V staging: thread owns (key = tid&63, d-range db..db+32) ----
    const int key = tid & 63;
    const int db  = (tid >> 6) * 32;
    uint32_t kstg[16], vstg[16];

    #define LDG_KV(t) do {                                                      \
        const float4* kp = (const float4*)(kb + ((size_t)(t) * 64 + key) * HDIM + db); \
        const float4* vp = (const float4*)(vb + ((size_t)(t) * 64 + key) * HDIM + db); \
        _Pragma("unroll")                                                       \
        for (int i = 0; i < 8; i++) {                                           \
            float4 f = kp[i];                                                   \
            kstg[2 * i]     = f2h2(f.x, f.y);                                   \
            kstg[2 * i + 1] = f2h2(f.z, f.w);                                   \
            f = vp[i];                                                          \
            vstg[2 * i]     = f2h2(f.x, f.y);                                   \
            vstg[2 * i + 1] = f2h2(f.z, f.w);                                   \
        }                                                                       \
    } while (0)

    #define STS_KV(s) do {                                                      \
        _Pragma("unroll")                                                       \
        for (int i = 0; i < 16; i++)                                            \
            *(uint32_t*)&Ks[s][key][db + 2 * i] = kstg[i];                      \
        _Pragma("unroll")                                                       \
        for (int i = 0; i < 16; i++) {                                          \
            __half2 hh = *(__half2*)&vstg[i];                                   \
            Vt[s][db + 2 * i    ][key] = __low2half(hh);                        \
            Vt[s][db + 2 * i + 1][key] = __high2half(hh);                       \
        }                                                                       \
    } while (0)

    LDG_KV(0);
    STS_KV(0);
    LDG_KV(1);
    __syncthreads();

    // ---- Q fragments to registers (rows wid*16 + gid / +8) ----
    uint32_t aq[4][4];
    {
        const int r = wid * 16 + gid;
        #pragma unroll
        for (int ks = 0; ks < 4; ks++) {
            aq[ks][0] = *(const uint32_t*)&Qs[r    ][16 * ks + 2 * tid4    ];
            aq[ks][1] = *(const uint32_t*)&Qs[r + 8][16 * ks + 2 * tid4    ];
            aq[ks][2] = *(const uint32_t*)&Qs[r    ][16 * ks + 2 * tid4 + 8];
            aq[ks][3] = *(const uint32_t*)&Qs[r + 8][16 * ks + 2 * tid4 + 8];
        }
    }

    float m0 = -1e30f, m1 = -1e30f, l0 = 0.f, l1 = 0.f;
    float oacc[8][4] = {};

    for (int t = 0; t < 32; t++) {
        const int s = t & 1;

        // ---- S = Q K^T : 8 n-tiles of 8 keys ----
        float sacc[8][4] = {};
        #pragma unroll
        for (int ks = 0; ks < 4; ks++) {
            #pragma unroll
            for (int j = 0; j < 8; j++) {
                uint32_t bf[2];
                bf[0] = *(const uint32_t*)&Ks[s][8 * j + gid][16 * ks + 2 * tid4    ];
                bf[1] = *(const uint32_t*)&Ks[s][8 * j + gid][16 * ks + 2 * tid4 + 8];
                mma16816(sacc[j], aq[ks], bf);
            }
        }

        // ---- online softmax (row gid -> frag 0,1; row gid+8 -> frag 2,3) ----
        float mx0 = -1e30f, mx1 = -1e30f;
        #pragma unroll
        for (int j = 0; j < 8; j++) {
            mx0 = fmaxf(mx0, fmaxf(sacc[j][0], sacc[j][1]));
            mx1 = fmaxf(mx1, fmaxf(sacc[j][2], sacc[j][3]));
        }
        #pragma unroll
        for (int off = 1; off <= 2; off <<= 1) {
            mx0 = fmaxf(mx0, __shfl_xor_sync(0xffffffffu, mx0, off));
            mx1 = fmaxf(mx1, __shfl_xor_sync(0xffffffffu, mx1, off));
        }
        const float mn0 = fmaxf(m0, mx0);
        const float mn1 = fmaxf(m1, mx1);
        const float sc0 = __expf(m0 - mn0);
        const float sc1 = __expf(m1 - mn1);

        float rs0 = 0.f, rs1 = 0.f;
        #pragma unroll
        for (int j = 0; j < 8; j++) {
            sacc[j][0] = __expf(sacc[j][0] - mn0);
            sacc[j][1] = __expf(sacc[j][1] - mn0);
            sacc[j][2] = __expf(sacc[j][2] - mn1);
            sacc[j][3] = __expf(sacc[j][3] - mn1);
            rs0 += sacc[j][0] + sacc[j][1];
            rs1 += sacc[j][2] + sacc[j][3];
        }
        #pragma unroll
        for (int off = 1; off <= 2; off <<= 1) {
            rs0 += __shfl_xor_sync(0xffffffffu, rs0, off);
            rs1 += __shfl_xor_sync(0xffffffffu, rs1, off);
        }
        l0 = l0 * sc0 + rs0;  m0 = mn0;
        l1 = l1 * sc1 + rs1;  m1 = mn1;

        #pragma unroll
        for (int j = 0; j < 8; j++) {
            oacc[j][0] *= sc0;  oacc[j][1] *= sc0;
            oacc[j][2] *= sc1;  oacc[j][3] *= sc1;
        }

        // ---- P (C-frag) -> A-frag repack, registers only ----
        uint32_t ap[4][4];
        #pragma unroll
        for (int ks = 0; ks < 4; ks++) {
            ap[ks][0] = f2h2(sacc[2 * ks][0],     sacc[2 * ks][1]);
            ap[ks][1] = f2h2(sacc[2 * ks][2],     sacc[2 * ks][3]);
            ap[ks][2] = f2h2(sacc[2 * ks + 1][0], sacc[2 * ks + 1][1]);
            ap[ks][3] = f2h2(sacc[2 * ks + 1][2], sacc[2 * ks + 1][3]);
        }

        // ---- O += P V : 8 d-tiles of 8 ----
        #pragma unroll
        for (int ks = 0; ks < 4; ks++) {
            #pragma unroll
            for (int j = 0; j < 8; j++) {
                uint32_t bf[2];
                bf[0] = *(const uint32_t*)&Vt[s][8 * j + gid][16 * ks + 2 * tid4    ];
                bf[1] = *(const uint32_t*)&Vt[s][8 * j + gid][16 * ks + 2 * tid4 + 8];
                mma16816(oacc[j], ap[ks], bf);
            }
        }

        // ---- pipeline next tile ----
        if (t + 1 < 32) STS_KV((t + 1) & 1);
        if (t + 2 < 32) LDG_KV(t + 2);
        __syncthreads();
    }

    // ---- normalize + write ctx [B,S,H*dh] ----
    const int r = q0 + wid * 16 + gid;
    const float inv0 = 1.f / l0;
    const float inv1 = 1.f / l1;
    #pragma unroll
    for (int j = 0; j < 8; j++) {
        const int d = h * HDIM + 8 * j + 2 * tid4;
        float2 v0 = { oacc[j][0] * inv0, oacc[j][1] * inv0 };
        float2 v1 = { oacc[j][2] * inv1, oacc[j][3] * inv1 };
        *(float2*)&ctx[((size_t)(b * SEQ + r))     * MDIM + d] = v0;
        *(float2*)&ctx[((size_t)(b * SEQ + r + 8)) * MDIM + d] = v1;
    }
}

// ---------------- launch ----------------------------------------------------
extern "C" void kernel_launch(void* const* d_in, const int* in_sizes, int n_in,
                              void* d_out, int out_size) {
    const float* q  = (const float*)d_in[0];
    const float* k  = (const float*)d_in[1];
    const float* v  = (const float*)d_in[2];
    const float* wq = (const float*)d_in[3];
    const float* wk = (const float*)d_in[4];
    const float* wv = (const float*)d_in[5];
    const float* wo = (const float*)d_in[6];
    float* out = (float*)d_out;

    float *qh, *kh, *vh, *ctx;
    cudaGetSymbolAddress((void**)&qh,  g_qh);
    cudaGetSymbolAddress((void**)&kh,  g_kh);
    cudaGetSymbolAddress((void**)&vh,  g_vh);
    cudaGetSymbolAddress((void**)&ctx, g_ctx);

    dim3 gridP(MDIM / 128, MROWS / 128);   // (8, 64)
    gemm_mma<true ><<<gridP, 256>>>(q, wq, qh);
    gemm_mma<true ><<<gridP, 256>>>(k, wk, kh);
    gemm_mma<true ><<<gridP, 256>>>(v, wv, vh);

    dim3 gridF(SEQ / 64, BATCH * NHEADS);  // (32, 64)
    flash_mma<<<gridF, 128>>>(qh, kh, vh, ctx);

    gemm_mma<false><<<gridP, 256>>>(ctx, wo, out);
}

// round 7
// speedup vs baseline: 5.5594x; 1.4883x over previous
#include <cuda_runtime.h>
#include <cuda_fp16.h>
#include <cstdint>

#define MDIM   1024
#define NHEADS 16
#define HDIM   64
#define BATCH  4
#define SEQ    2048
#define MROWS  (BATCH * SEQ)   // 8192

__device__ __align__(16) __half g_qh[BATCH * NHEADS * SEQ * HDIM];  // [B,H,S,dh] fp16, pre-scaled
__device__ __align__(16) __half g_kh[BATCH * NHEADS * SEQ * HDIM];
__device__ __align__(16) __half g_vh[BATCH * NHEADS * SEQ * HDIM];
__device__ __align__(16) float  g_ctx[BATCH * SEQ * MDIM];          // [B,S,H*dh] fp32

// ---------------- helpers ----------------------------------------------------
__device__ __forceinline__ void mma16816(float* d, const uint32_t* a,
                                         const uint32_t* b) {
    asm volatile(
        "mma.sync.aligned.m16n8k16.row.col.f32.f16.f16.f32 "
        "{%0,%1,%2,%3}, {%4,%5,%6,%7}, {%8,%9}, {%0,%1,%2,%3};"
        : "+f"(d[0]), "+f"(d[1]), "+f"(d[2]), "+f"(d[3])
        : "r"(a[0]), "r"(a[1]), "r"(a[2]), "r"(a[3]),
          "r"(b[0]), "r"(b[1]));
}
__device__ __forceinline__ uint32_t f2h2(float x, float y) {
    __half2 h = __floats2half2_rn(x, y);
    return *(uint32_t*)&h;
}
__device__ __forceinline__ uint32_t smem_u32(const void* p) {
    uint32_t a;
    asm("{ .reg .u64 t; cvta.to.shared.u64 t, %1; cvt.u32.u64 %0, t; }"
        : "=r"(a) : "l"(p));
    return a;
}
#define CP_ASYNC16(dst, src) \
    asm volatile("cp.async.ca.shared.global [%0], [%1], 16;" \
                 :: "r"(dst), "l"(src) : "memory")
#define CP_COMMIT  asm volatile("cp.async.commit_group;" ::: "memory")
#define CP_WAIT0   asm volatile("cp.async.wait_group 0;" ::: "memory")
#define CP_WAIT1   asm volatile("cp.async.wait_group 1;" ::: "memory")

// ---------------- fp16 tensor-core GEMM --------------------------------------
// C = A(M,1024) * W(1024,1024)^T.
// HEAD_OUT: write half2 (scaled) into head layout Ch; else float2 into Cf.
#define LDS_H 40

template<bool HEAD_OUT>
__global__ __launch_bounds__(256)
void gemm_mma(const float* __restrict__ A,
              const float* __restrict__ W,
              float* __restrict__ Cf,
              __half* __restrict__ Ch,
              float scale) {
    __shared__ __align__(16) __half As[2][128][LDS_H];
    __shared__ __align__(16) __half Ws[2][128][LDS_H];

    const int tid  = threadIdx.x;
    const int wid  = tid >> 5;
    const int lane = tid & 31;
    const int gid  = lane >> 2;
    const int tid4 = lane & 3;
    const int wm   = (wid >> 2) * 64;
    const int wn   = (wid & 3) * 32;
    const int bm   = blockIdx.y * 128;
    const int bn   = blockIdx.x * 128;

    const int lrow = tid >> 3;
    const int c4   = tid & 7;
    const float* gA = A + (size_t)(bm + lrow) * MDIM + c4 * 4;
    const float* gW = W + (size_t)(bn + lrow) * MDIM + c4 * 4;

    float4 ra[4], rw[4];

    #define LDG_STAGE(kt) do {                                                 \
        const int _k0 = (kt) * 32;                                             \
        _Pragma("unroll")                                                      \
        for (int j = 0; j < 4; j++) {                                          \
            ra[j] = *(const float4*)(gA + (size_t)(j * 32) * MDIM + _k0);      \
            rw[j] = *(const float4*)(gW + (size_t)(j * 32) * MDIM + _k0);      \
        }                                                                      \
    } while (0)

    #define STS_STAGE(s) do {                                                  \
        _Pragma("unroll")                                                      \
        for (int j = 0; j < 4; j++) {                                          \
            uint2 av = { f2h2(ra[j].x, ra[j].y), f2h2(ra[j].z, ra[j].w) };     \
            uint2 wv = { f2h2(rw[j].x, rw[j].y), f2h2(rw[j].z, rw[j].w) };     \
            *(uint2*)&As[s][lrow + j * 32][c4 * 4] = av;                       \
            *(uint2*)&Ws[s][lrow + j * 32][c4 * 4] = wv;                       \
        }                                                                      \
    } while (0)

    float acc[4][4][4] = {};

    LDG_STAGE(0);
    STS_STAGE(0);
    __syncthreads();

    for (int kt = 0; kt < 32; kt++) {
        const int cur = kt & 1;
        if (kt + 1 < 32) LDG_STAGE(kt + 1);

        #pragma unroll
        for (int ks = 0; ks < 2; ks++) {
            const int kh = ks * 16;
            uint32_t af[4][4], bf[4][2];
            #pragma unroll
            for (int i = 0; i < 4; i++) {
                const int r = wm + i * 16 + gid;
                af[i][0] = *(const uint32_t*)&As[cur][r    ][kh + 2 * tid4    ];
                af[i][1] = *(const uint32_t*)&As[cur][r + 8][kh + 2 * tid4    ];
                af[i][2] = *(const uint32_t*)&As[cur][r    ][kh + 2 * tid4 + 8];
                af[i][3] = *(const uint32_t*)&As[cur][r + 8][kh + 2 * tid4 + 8];
            }
            #pragma unroll
            for (int j = 0; j < 4; j++) {
                const int n = wn + j * 8 + gid;
                bf[j][0] = *(const uint32_t*)&Ws[cur][n][kh + 2 * tid4    ];
                bf[j][1] = *(const uint32_t*)&Ws[cur][n][kh + 2 * tid4 + 8];
            }
            #pragma unroll
            for (int i = 0; i < 4; i++)
                #pragma unroll
                for (int j = 0; j < 4; j++)
                    mma16816(acc[i][j], af[i], bf[j]);
        }

        __syncthreads();
        if (kt + 1 < 32) {
            STS_STAGE(cur ^ 1);
            __syncthreads();
        }
    }

    #pragma unroll
    for (int i = 0; i < 4; i++) {
        #pragma unroll
        for (int j = 0; j < 4; j++) {
            const int n = bn + wn + j * 8 + 2 * tid4;
            #pragma unroll
            for (int half_ = 0; half_ < 2; half_++) {
                const int m = bm + wm + i * 16 + gid + half_ * 8;
                float vx = acc[i][j][half_ * 2];
                float vy = acc[i][j][half_ * 2 + 1];
                if (HEAD_OUT) {
                    const int bb = m >> 11, ss = m & 2047;
                    const int hh = n >> 6,  dd = n & 63;
                    uint32_t hv = f2h2(vx * scale, vy * scale);
                    *(uint32_t*)&Ch[(((size_t)(bb * NHEADS + hh) * SEQ) + ss) * HDIM + dd] = hv;
                } else {
                    float2 v = { vx, vy };
                    *(float2*)&Cf[(size_t)m * MDIM + n] = v;
                }
            }
        }
    }
}

// ---------------- tensor-core flash attention --------------------------------
// 128 threads / 4 warps; Q-tile 128x64 (warp owns 32 rows = two m16 A-tiles);
// 32 key-tiles of 64. K row-major via cp.async; V transposed via reg staging.
// Every K/V B-fragment feeds 2 mma (the two A-tiles).
#define FH 72

__global__ __launch_bounds__(128)
void flash_mma(const __half* __restrict__ qh,
               const __half* __restrict__ kh,
               const __half* __restrict__ vh,
               float* __restrict__ ctx) {
    __shared__ __align__(16) __half Ks[2][64][FH];
    __shared__ __align__(16) __half Vt[2][64][FH];

    const int tid  = threadIdx.x;
    const int wid  = tid >> 5;
    const int lane = tid & 31;
    const int gid  = lane >> 2;
    const int tid4 = lane & 3;

    const int bh = blockIdx.y;
    const int b  = bh >> 4;
    const int h  = bh & 15;
    const int q0 = blockIdx.x * 128;

    const __half* qb = qh + (size_t)bh * SEQ * HDIM;
    const __half* kb = kh + (size_t)bh * SEQ * HDIM;
    const __half* vb = vh + (size_t)bh * SEQ * HDIM;

    // per-thread KV slots: key = tid&63, d-range dbase..dbase+31
    const int key   = tid & 63;
    const int dbase = (tid >> 6) * 32;

    // cp.async K: 4 x 16B per thread per tile
    #define CPK(t, s) do {                                                      \
        const __half* _src = kb + ((size_t)(t) * 64 + key) * HDIM + dbase;      \
        uint32_t _dst = smem_u32(&Ks[s][key][dbase]);                           \
        _Pragma("unroll")                                                       \
        for (int i = 0; i < 4; i++)                                             \
            CP_ASYNC16(_dst + 16 * i, _src + 8 * i);                            \
    } while (0)

    uint4 vstg[4];
    #define VLD(t) do {                                                         \
        const uint4* _vp = (const uint4*)(vb + ((size_t)(t) * 64 + key) * HDIM + dbase); \
        _Pragma("unroll")                                                       \
        for (int i = 0; i < 4; i++) vstg[i] = _vp[i];                           \
    } while (0)

    #define VST(s) do {                                                         \
        _Pragma("unroll")                                                       \
        for (int i = 0; i < 4; i++) {                                           \
            const __half* _hp = (const __half*)&vstg[i];                        \
            _Pragma("unroll")                                                   \
            for (int j = 0; j < 8; j++)                                         \
                Vt[s][dbase + 8 * i + j][key] = _hp[j];                         \
        }                                                                       \
    } while (0)

    // ---- Q fragments straight from gmem (2 A-tiles x 4 k-steps) ----
    uint32_t aq[2][4][4];
    {
        const __half* qrow = qb + (size_t)q0 * HDIM;
        #pragma unroll
        for (int ia = 0; ia < 2; ia++) {
            const int r = wid * 32 + ia * 16 + gid;
            #pragma unroll
            for (int ks = 0; ks < 4; ks++) {
                const int kc = 16 * ks + 2 * tid4;
                aq[ia][ks][0] = *(const uint32_t*)(qrow + (size_t)r * HDIM + kc);
                aq[ia][ks][1] = *(const uint32_t*)(qrow + (size_t)(r + 8) * HDIM + kc);
                aq[ia][ks][2] = *(const uint32_t*)(qrow + (size_t)r * HDIM + kc + 8);
                aq[ia][ks][3] = *(const uint32_t*)(qrow + (size_t)(r + 8) * HDIM + kc + 8);
            }
        }
    }

    float m[2][2], l[2][2];
    #pragma unroll
    for (int ia = 0; ia < 2; ia++) {
        m[ia][0] = -1e30f; m[ia][1] = -1e30f;
        l[ia][0] = 0.f;    l[ia][1] = 0.f;
    }
    float oacc[2][8][4] = {};

    // ---- prologue ----
    CPK(0, 0); CP_COMMIT;
    VLD(0);
    CPK(1, 1); CP_COMMIT;
    CP_WAIT1;                 // K(0) landed, K(1) in flight
    VST(0);
    VLD(1);
    __syncthreads();

    for (int t = 0; t < 32; t++) {
        const int s = t & 1;

        // ---- S = Q K^T : shared bf feeds both A-tiles ----
        float sacc[2][8][4] = {};
        #pragma unroll
        for (int ks = 0; ks < 4; ks++) {
            #pragma unroll
            for (int j = 0; j < 8; j++) {
                uint32_t bf[2];
                bf[0] = *(const uint32_t*)&Ks[s][8 * j + gid][16 * ks + 2 * tid4    ];
                bf[1] = *(const uint32_t*)&Ks[s][8 * j + gid][16 * ks + 2 * tid4 + 8];
                mma16816(sacc[0][j], aq[0][ks], bf);
                mma16816(sacc[1][j], aq[1][ks], bf);
            }
        }

        // ---- online softmax per A-tile ----
        uint32_t ap[2][4][4];
        #pragma unroll
        for (int ia = 0; ia < 2; ia++) {
            float mx0 = -1e30f, mx1 = -1e30f;
            #pragma unroll
            for (int j = 0; j < 8; j++) {
                mx0 = fmaxf(mx0, fmaxf(sacc[ia][j][0], sacc[ia][j][1]));
                mx1 = fmaxf(mx1, fmaxf(sacc[ia][j][2], sacc[ia][j][3]));
            }
            #pragma unroll
            for (int off = 1; off <= 2; off <<= 1) {
                mx0 = fmaxf(mx0, __shfl_xor_sync(0xffffffffu, mx0, off));
                mx1 = fmaxf(mx1, __shfl_xor_sync(0xffffffffu, mx1, off));
            }
            const float mn0 = fmaxf(m[ia][0], mx0);
            const float mn1 = fmaxf(m[ia][1], mx1);
            const float sc0 = __expf(m[ia][0] - mn0);
            const float sc1 = __expf(m[ia][1] - mn1);

            float rs0 = 0.f, rs1 = 0.f;
            #pragma unroll
            for (int j = 0; j < 8; j++) {
                sacc[ia][j][0] = __expf(sacc[ia][j][0] - mn0);
                sacc[ia][j][1] = __expf(sacc[ia][j][1] - mn0);
                sacc[ia][j][2] = __expf(sacc[ia][j][2] - mn1);
                sacc[ia][j][3] = __expf(sacc[ia][j][3] - mn1);
                rs0 += sacc[ia][j][0] + sacc[ia][j][1];
                rs1 += sacc[ia][j][2] + sacc[ia][j][3];
            }
            #pragma unroll
            for (int off = 1; off <= 2; off <<= 1) {
                rs0 += __shfl_xor_sync(0xffffffffu, rs0, off);
                rs1 += __shfl_xor_sync(0xffffffffu, rs1, off);
            }
            l[ia][0] = l[ia][0] * sc0 + rs0;  m[ia][0] = mn0;
            l[ia][1] = l[ia][1] * sc1 + rs1;  m[ia][1] = mn1;

            #pragma unroll
            for (int j = 0; j < 8; j++) {
                oacc[ia][j][0] *= sc0;  oacc[ia][j][1] *= sc0;
                oacc[ia][j][2] *= sc1;  oacc[ia][j][3] *= sc1;
            }
            // P C-frag -> A-frag repack (verified layout)
            #pragma unroll
            for (int ks = 0; ks < 4; ks++) {
                ap[ia][ks][0] = f2h2(sacc[ia][2 * ks][0],     sacc[ia][2 * ks][1]);
                ap[ia][ks][1] = f2h2(sacc[ia][2 * ks][2],     sacc[ia][2 * ks][3]);
                ap[ia][ks][2] = f2h2(sacc[ia][2 * ks + 1][0], sacc[ia][2 * ks + 1][1]);
                ap[ia][ks][3] = f2h2(sacc[ia][2 * ks + 1][2], sacc[ia][2 * ks + 1][3]);
            }
        }

        // ---- O += P V : shared bf feeds both A-tiles ----
        #pragma unroll
        for (int ks = 0; ks < 4; ks++) {
            #pragma unroll
            for (int j = 0; j < 8; j++) {
                uint32_t bf[2];
                bf[0] = *(const uint32_t*)&Vt[s][8 * j + gid][16 * ks + 2 * tid4    ];
                bf[1] = *(const uint32_t*)&Vt[s][8 * j + gid][16 * ks + 2 * tid4 + 8];
                mma16816(oacc[0][j], ap[0][ks], bf);
                mma16816(oacc[1][j], ap[1][ks], bf);
            }
        }

        // ---- pipeline ----
        if (t + 1 < 32) VST((t + 1) & 1);
        CP_WAIT0;                // K(t+1) landed
        __syncthreads();         // readers done with buf s; K/V(t+1) visible
        if (t + 2 < 32) {
            CPK(t + 2, s); CP_COMMIT;
            VLD(t + 2);
        }
    }

    // ---- normalize + write ctx [B,S,H*dh] ----
    #pragma unroll
    for (int ia = 0; ia < 2; ia++) {
        const int r = q0 + wid * 32 + ia * 16 + gid;
        const float inv0 = 1.f / l[ia][0];
        const float inv1 = 1.f / l[ia][1];
        #pragma unroll
        for (int j = 0; j < 8; j++) {
            const int d = h * HDIM + 8 * j + 2 * tid4;
            float2 v0 = { oacc[ia][j][0] * inv0, oacc[ia][j][1] * inv0 };
            float2 v1 = { oacc[ia][j][2] * inv1, oacc[ia][j][3] * inv1 };
            *(float2*)&ctx[((size_t)(b * SEQ + r))     * MDIM + d] = v0;
            *(float2*)&ctx[((size_t)(b * SEQ + r + 8)) * MDIM + d] = v1;
        }
    }
}

// ---------------- launch ------------------------------------------------------
extern "C" void kernel_launch(void* const* d_in, const int* in_sizes, int n_in,
                              void* d_out, int out_size) {
    const float* q  = (const float*)d_in[0];
    const float* k  = (const float*)d_in[1];
    const float* v  = (const float*)d_in[2];
    const float* wq = (const float*)d_in[3];
    const float* wk = (const float*)d_in[4];
    const float* wv = (const float*)d_in[5];
    const float* wo = (const float*)d_in[6];
    float* out = (float*)d_out;

    __half *qh, *kh, *vh;
    float *ctx;
    cudaGetSymbolAddress((void**)&qh,  g_qh);
    cudaGetSymbolAddress((void**)&kh,  g_kh);
    cudaGetSymbolAddress((void**)&vh,  g_vh);
    cudaGetSymbolAddress((void**)&ctx, g_ctx);

    dim3 gridP(MDIM / 128, MROWS / 128);   // (8, 64)
    gemm_mma<true ><<<gridP, 256>>>(q, wq, nullptr, qh, 0.125f);
    gemm_mma<true ><<<gridP, 256>>>(k, wk, nullptr, kh, 1.0f);
    gemm_mma<true ><<<gridP, 256>>>(v, wv, nullptr, vh, 1.0f);

    dim3 gridF(SEQ / 128, BATCH * NHEADS); // (16, 64)
    flash_mma<<<gridF, 128>>>(qh, kh, vh, ctx);

    gemm_mma<false><<<gridP, 256>>>(ctx, wo, out, nullptr, 1.0f);
}

// round 8
// speedup vs baseline: 6.3967x; 1.1506x over previous
#include <cuda_runtime.h>
#include <cuda_fp16.h>
#include <cstdint>

#define MDIM   1024
#define NHEADS 16
#define HDIM   64
#define BATCH  4
#define SEQ    2048
#define MROWS  (BATCH * SEQ)   // 8192

__device__ __align__(16) __half g_qh[BATCH * NHEADS * SEQ * HDIM];  // [B,H,S,dh] fp16, pre-scaled
__device__ __align__(16) __half g_kh[BATCH * NHEADS * SEQ * HDIM];
__device__ __align__(16) __half g_vh[BATCH * NHEADS * SEQ * HDIM];
__device__ __align__(16) float  g_ctx[BATCH * SEQ * MDIM];          // [B,S,H*dh] fp32

// ---------------- helpers ----------------------------------------------------
__device__ __forceinline__ void mma16816(float* d, const uint32_t* a,
                                         const uint32_t* b) {
    asm volatile(
        "mma.sync.aligned.m16n8k16.row.col.f32.f16.f16.f32 "
        "{%0,%1,%2,%3}, {%4,%5,%6,%7}, {%8,%9}, {%0,%1,%2,%3};"
        : "+f"(d[0]), "+f"(d[1]), "+f"(d[2]), "+f"(d[3])
        : "r"(a[0]), "r"(a[1]), "r"(a[2]), "r"(a[3]),
          "r"(b[0]), "r"(b[1]));
}
__device__ __forceinline__ uint32_t f2h2(float x, float y) {
    __half2 h = __floats2half2_rn(x, y);
    return *(uint32_t*)&h;
}
__device__ __forceinline__ uint32_t smem_u32(const void* p) {
    uint32_t a;
    asm("{ .reg .u64 t; cvta.to.shared.u64 t, %1; cvt.u32.u64 %0, t; }"
        : "=r"(a) : "l"(p));
    return a;
}
__device__ __forceinline__ void ldmx4(uint32_t* r, uint32_t addr) {
    asm volatile("ldmatrix.sync.aligned.m8n8.x4.shared.b16 {%0,%1,%2,%3}, [%4];"
                 : "=r"(r[0]), "=r"(r[1]), "=r"(r[2]), "=r"(r[3]) : "r"(addr));
}
__device__ __forceinline__ void ldmx4t(uint32_t* r, uint32_t addr) {
    asm volatile("ldmatrix.sync.aligned.m8n8.x4.trans.shared.b16 {%0,%1,%2,%3}, [%4];"
                 : "=r"(r[0]), "=r"(r[1]), "=r"(r[2]), "=r"(r[3]) : "r"(addr));
}
#define CP_ASYNC16(dst, src) \
    asm volatile("cp.async.ca.shared.global [%0], [%1], 16;" \
                 :: "r"(dst), "l"(src) : "memory")
#define CP_COMMIT  asm volatile("cp.async.commit_group;" ::: "memory")
#define CP_WAIT0   asm volatile("cp.async.wait_group 0;" ::: "memory")
#define CP_WAIT1   asm volatile("cp.async.wait_group 1;" ::: "memory")

// ---------------- fp16 tensor-core GEMM (unchanged, verified) ----------------
#define LDS_H 40

template<bool HEAD_OUT>
__global__ __launch_bounds__(256)
void gemm_mma(const float* __restrict__ A,
              const float* __restrict__ W,
              float* __restrict__ Cf,
              __half* __restrict__ Ch,
              float scale) {
    __shared__ __align__(16) __half As[2][128][LDS_H];
    __shared__ __align__(16) __half Ws[2][128][LDS_H];

    const int tid  = threadIdx.x;
    const int wid  = tid >> 5;
    const int lane = tid & 31;
    const int gid  = lane >> 2;
    const int tid4 = lane & 3;
    const int wm   = (wid >> 2) * 64;
    const int wn   = (wid & 3) * 32;
    const int bm   = blockIdx.y * 128;
    const int bn   = blockIdx.x * 128;

    const int lrow = tid >> 3;
    const int c4   = tid & 7;
    const float* gA = A + (size_t)(bm + lrow) * MDIM + c4 * 4;
    const float* gW = W + (size_t)(bn + lrow) * MDIM + c4 * 4;

    float4 ra[4], rw[4];

    #define LDG_STAGE(kt) do {                                                 \
        const int _k0 = (kt) * 32;                                             \
        _Pragma("unroll")                                                      \
        for (int j = 0; j < 4; j++) {                                          \
            ra[j] = *(const float4*)(gA + (size_t)(j * 32) * MDIM + _k0);      \
            rw[j] = *(const float4*)(gW + (size_t)(j * 32) * MDIM + _k0);      \
        }                                                                      \
    } while (0)

    #define STS_STAGE(s) do {                                                  \
        _Pragma("unroll")                                                      \
        for (int j = 0; j < 4; j++) {                                          \
            uint2 av = { f2h2(ra[j].x, ra[j].y), f2h2(ra[j].z, ra[j].w) };     \
            uint2 wv = { f2h2(rw[j].x, rw[j].y), f2h2(rw[j].z, rw[j].w) };     \
            *(uint2*)&As[s][lrow + j * 32][c4 * 4] = av;                       \
            *(uint2*)&Ws[s][lrow + j * 32][c4 * 4] = wv;                       \
        }                                                                      \
    } while (0)

    float acc[4][4][4] = {};

    LDG_STAGE(0);
    STS_STAGE(0);
    __syncthreads();

    for (int kt = 0; kt < 32; kt++) {
        const int cur = kt & 1;
        if (kt + 1 < 32) LDG_STAGE(kt + 1);

        #pragma unroll
        for (int ks = 0; ks < 2; ks++) {
            const int kh = ks * 16;
            uint32_t af[4][4], bf[4][2];
            #pragma unroll
            for (int i = 0; i < 4; i++) {
                const int r = wm + i * 16 + gid;
                af[i][0] = *(const uint32_t*)&As[cur][r    ][kh + 2 * tid4    ];
                af[i][1] = *(const uint32_t*)&As[cur][r + 8][kh + 2 * tid4    ];
                af[i][2] = *(const uint32_t*)&As[cur][r    ][kh + 2 * tid4 + 8];
                af[i][3] = *(const uint32_t*)&As[cur][r + 8][kh + 2 * tid4 + 8];
            }
            #pragma unroll
            for (int j = 0; j < 4; j++) {
                const int n = wn + j * 8 + gid;
                bf[j][0] = *(const uint32_t*)&Ws[cur][n][kh + 2 * tid4    ];
                bf[j][1] = *(const uint32_t*)&Ws[cur][n][kh + 2 * tid4 + 8];
            }
            #pragma unroll
            for (int i = 0; i < 4; i++)
                #pragma unroll
                for (int j = 0; j < 4; j++)
                    mma16816(acc[i][j], af[i], bf[j]);
        }

        __syncthreads();
        if (kt + 1 < 32) {
            STS_STAGE(cur ^ 1);
            __syncthreads();
        }
    }

    #pragma unroll
    for (int i = 0; i < 4; i++) {
        #pragma unroll
        for (int j = 0; j < 4; j++) {
            const int n = bn + wn + j * 8 + 2 * tid4;
            #pragma unroll
            for (int half_ = 0; half_ < 2; half_++) {
                const int m = bm + wm + i * 16 + gid + half_ * 8;
                float vx = acc[i][j][half_ * 2];
                float vy = acc[i][j][half_ * 2 + 1];
                if (HEAD_OUT) {
                    const int bb = m >> 11, ss = m & 2047;
                    const int hh = n >> 6,  dd = n & 63;
                    uint32_t hv = f2h2(vx * scale, vy * scale);
                    *(uint32_t*)&Ch[(((size_t)(bb * NHEADS + hh) * SEQ) + ss) * HDIM + dd] = hv;
                } else {
                    float2 v = { vx, vy };
                    *(float2*)&Cf[(size_t)m * MDIM + n] = v;
                }
            }
        }
    }
}

// ---------------- tensor-core flash attention ---------------------------------
// 128 threads / 4 warps; Q-tile 128x64 (2 m16 A-tiles per warp); 32 key-tiles.
// K AND V row-major [key][d] via cp.async; B-frags via ldmatrix.x4 (K) and
// ldmatrix.x4.trans (V). P stays in registers.
#define FH 72

__global__ __launch_bounds__(128)
void flash_mma(const __half* __restrict__ qh,
               const __half* __restrict__ kh,
               const __half* __restrict__ vh,
               float* __restrict__ ctx) {
    __shared__ __align__(16) __half Ks[2][64][FH];
    __shared__ __align__(16) __half Vs[2][64][FH];

    const int tid  = threadIdx.x;
    const int wid  = tid >> 5;
    const int lane = tid & 31;
    const int gid  = lane >> 2;
    const int tid4 = lane & 3;

    const int bh = blockIdx.y;
    const int b  = bh >> 4;
    const int h  = bh & 15;
    const int q0 = blockIdx.x * 128;

    const __half* qb = qh + (size_t)bh * SEQ * HDIM;
    const __half* kb = kh + (size_t)bh * SEQ * HDIM;
    const __half* vb = vh + (size_t)bh * SEQ * HDIM;

    // per-thread cp.async slot: key = tid&63, d-range dbase..dbase+31
    const int key   = tid & 63;
    const int dbase = (tid >> 6) * 32;
    const uint32_t ksm[2] = { smem_u32(&Ks[0][key][dbase]), smem_u32(&Ks[1][key][dbase]) };
    const uint32_t vsm[2] = { smem_u32(&Vs[0][key][dbase]), smem_u32(&Vs[1][key][dbase]) };

    #define CPKV(t, s) do {                                                     \
        const __half* _ks = kb + ((size_t)(t) * 64 + key) * HDIM + dbase;       \
        const __half* _vs = vb + ((size_t)(t) * 64 + key) * HDIM + dbase;       \
        _Pragma("unroll")                                                       \
        for (int i = 0; i < 4; i++) {                                           \
            CP_ASYNC16(ksm[s] + 16 * i, _ks + 8 * i);                           \
            CP_ASYNC16(vsm[s] + 16 * i, _vs + 8 * i);                           \
        }                                                                       \
    } while (0)

    // ldmatrix per-lane address components (g = lane>>3, rl = lane&7)
    const int g  = lane >> 3;
    const int rl = lane & 7;
    // K x4 per (ks, jp): matrices (j=2jp+g/2, khalf=g&1); row in mat = rl
    const uint32_t koff = (uint32_t)(((g >> 1) * 8 + rl) * FH + 8 * (g & 1)) * 2u;
    // V x4.trans per (ks, jp): matrices (khalf=g&1, j=2jp+g/2); row = key
    const uint32_t voff = (uint32_t)((8 * (g & 1) + rl) * FH + 8 * (g >> 1)) * 2u;
    const uint32_t kbase[2] = { smem_u32(&Ks[0][0][0]) + koff, smem_u32(&Ks[1][0][0]) + koff };
    const uint32_t vbase[2] = { smem_u32(&Vs[0][0][0]) + voff, smem_u32(&Vs[1][0][0]) + voff };

    // ---- Q fragments straight from gmem (2 A-tiles x 4 k-steps) ----
    uint32_t aq[2][4][4];
    {
        const __half* qrow = qb + (size_t)q0 * HDIM;
        #pragma unroll
        for (int ia = 0; ia < 2; ia++) {
            const int r = wid * 32 + ia * 16 + gid;
            #pragma unroll
            for (int ks = 0; ks < 4; ks++) {
                const int kc = 16 * ks + 2 * tid4;
                aq[ia][ks][0] = *(const uint32_t*)(qrow + (size_t)r * HDIM + kc);
                aq[ia][ks][1] = *(const uint32_t*)(qrow + (size_t)(r + 8) * HDIM + kc);
                aq[ia][ks][2] = *(const uint32_t*)(qrow + (size_t)r * HDIM + kc + 8);
                aq[ia][ks][3] = *(const uint32_t*)(qrow + (size_t)(r + 8) * HDIM + kc + 8);
            }
        }
    }

    float m[2][2], l[2][2];
    #pragma unroll
    for (int ia = 0; ia < 2; ia++) {
        m[ia][0] = -1e30f; m[ia][1] = -1e30f;
        l[ia][0] = 0.f;    l[ia][1] = 0.f;
    }
    float oacc[2][8][4] = {};

    // ---- prologue: tiles 0 and 1 in flight ----
    CPKV(0, 0); CP_COMMIT;
    CPKV(1, 1); CP_COMMIT;
    CP_WAIT1;                 // tile 0 landed
    __syncthreads();

    for (int t = 0; t < 32; t++) {
        const int s = t & 1;

        // ---- S = Q K^T ----
        float sacc[2][8][4] = {};
        #pragma unroll
        for (int ks = 0; ks < 4; ks++) {
            #pragma unroll
            for (int jp = 0; jp < 4; jp++) {
                uint32_t bf[4];
                ldmx4(bf, kbase[s] + (uint32_t)(2 * jp * 8 * FH + 16 * ks) * 2u);
                mma16816(sacc[0][2 * jp],     aq[0][ks], bf);
                mma16816(sacc[1][2 * jp],     aq[1][ks], bf);
                mma16816(sacc[0][2 * jp + 1], aq[0][ks], bf + 2);
                mma16816(sacc[1][2 * jp + 1], aq[1][ks], bf + 2);
            }
        }

        // ---- online softmax per A-tile + P repack ----
        uint32_t ap[2][4][4];
        #pragma unroll
        for (int ia = 0; ia < 2; ia++) {
            float mx0 = -1e30f, mx1 = -1e30f;
            #pragma unroll
            for (int j = 0; j < 8; j++) {
                mx0 = fmaxf(mx0, fmaxf(sacc[ia][j][0], sacc[ia][j][1]));
                mx1 = fmaxf(mx1, fmaxf(sacc[ia][j][2], sacc[ia][j][3]));
            }
            #pragma unroll
            for (int off = 1; off <= 2; off <<= 1) {
                mx0 = fmaxf(mx0, __shfl_xor_sync(0xffffffffu, mx0, off));
                mx1 = fmaxf(mx1, __shfl_xor_sync(0xffffffffu, mx1, off));
            }
            const float mn0 = fmaxf(m[ia][0], mx0);
            const float mn1 = fmaxf(m[ia][1], mx1);
            const float sc0 = __expf(m[ia][0] - mn0);
            const float sc1 = __expf(m[ia][1] - mn1);

            float rs0 = 0.f, rs1 = 0.f;
            #pragma unroll
            for (int j = 0; j < 8; j++) {
                sacc[ia][j][0] = __expf(sacc[ia][j][0] - mn0);
                sacc[ia][j][1] = __expf(sacc[ia][j][1] - mn0);
                sacc[ia][j][2] = __expf(sacc[ia][j][2] - mn1);
                sacc[ia][j][3] = __expf(sacc[ia][j][3] - mn1);
                rs0 += sacc[ia][j][0] + sacc[ia][j][1];
                rs1 += sacc[ia][j][2] + sacc[ia][j][3];
            }
            #pragma unroll
            for (int off = 1; off <= 2; off <<= 1) {
                rs0 += __shfl_xor_sync(0xffffffffu, rs0, off);
                rs1 += __shfl_xor_sync(0xffffffffu, rs1, off);
            }
            l[ia][0] = l[ia][0] * sc0 + rs0;  m[ia][0] = mn0;
            l[ia][1] = l[ia][1] * sc1 + rs1;  m[ia][1] = mn1;

            #pragma unroll
            for (int j = 0; j < 8; j++) {
                oacc[ia][j][0] *= sc0;  oacc[ia][j][1] *= sc0;
                oacc[ia][j][2] *= sc1;  oacc[ia][j][3] *= sc1;
            }
            #pragma unroll
            for (int ks = 0; ks < 4; ks++) {
                ap[ia][ks][0] = f2h2(sacc[ia][2 * ks][0],     sacc[ia][2 * ks][1]);
                ap[ia][ks][1] = f2h2(sacc[ia][2 * ks][2],     sacc[ia][2 * ks][3]);
                ap[ia][ks][2] = f2h2(sacc[ia][2 * ks + 1][0], sacc[ia][2 * ks + 1][1]);
                ap[ia][ks][3] = f2h2(sacc[ia][2 * ks + 1][2], sacc[ia][2 * ks + 1][3]);
            }
        }

        // ---- O += P V ----
        #pragma unroll
        for (int ks = 0; ks < 4; ks++) {
            #pragma unroll
            for (int jp = 0; jp < 4; jp++) {
                uint32_t bf[4];
                ldmx4t(bf, vbase[s] + (uint32_t)(16 * ks * FH + 2 * jp * 8) * 2u);
                mma16816(oacc[0][2 * jp],     ap[0][ks], bf);
                mma16816(oacc[1][2 * jp],     ap[1][ks], bf);
                mma16816(oacc[0][2 * jp + 1], ap[0][ks], bf + 2);
                mma16816(oacc[1][2 * jp + 1], ap[1][ks], bf + 2);
            }
        }

        // ---- pipeline ----
        CP_WAIT0;                // tile t+1 landed
        __syncthreads();         // all warps done reading buffer s
        if (t + 2 < 32) {
            CPKV(t + 2, s); CP_COMMIT;
        }
    }

    // ---- normalize + write ctx [B,S,H*dh] ----
    #pragma unroll
    for (int ia = 0; ia < 2; ia++) {
        const int r = q0 + wid * 32 + ia * 16 + gid;
        const float inv0 = 1.f / l[ia][0];
        const float inv1 = 1.f / l[ia][1];
        #pragma unroll
        for (int j = 0; j < 8; j++) {
            const int d = h * HDIM + 8 * j + 2 * tid4;
            float2 v0 = { oacc[ia][j][0] * inv0, oacc[ia][j][1] * inv0 };
            float2 v1 = { oacc[ia][j][2] * inv1, oacc[ia][j][3] * inv1 };
            *(float2*)&ctx[((size_t)(b * SEQ + r))     * MDIM + d] = v0;
            *(float2*)&ctx[((size_t)(b * SEQ + r + 8)) * MDIM + d] = v1;
        }
    }
}

// ---------------- launch -------------------------------------------------------
extern "C" void kernel_launch(void* const* d_in, const int* in_sizes, int n_in,
                              void* d_out, int out_size) {
    const float* q  = (const float*)d_in[0];
    const float* k  = (const float*)d_in[1];
    const float* v  = (const float*)d_in[2];
    const float* wq = (const float*)d_in[3];
    const float* wk = (const float*)d_in[4];
    const float* wv = (const float*)d_in[5];
    const float* wo = (const float*)d_in[6];
    float* out = (float*)d_out;

    __half *qh, *kh, *vh;
    float *ctx;
    cudaGetSymbolAddress((void**)&qh,  g_qh);
    cudaGetSymbolAddress((void**)&kh,  g_kh);
    cudaGetSymbolAddress((void**)&vh,  g_vh);
    cudaGetSymbolAddress((void**)&ctx, g_ctx);

    dim3 gridP(MDIM / 128, MROWS / 128);   // (8, 64)
    gemm_mma<true ><<<gridP, 256>>>(q, wq, nullptr, qh, 0.125f);
    gemm_mma<true ><<<gridP, 256>>>(k, wk, nullptr, kh, 1.0f);
    gemm_mma<true ><<<gridP, 256>>>(v, wv, nullptr, vh, 1.0f);

    dim3 gridF(SEQ / 128, BATCH * NHEADS); // (16, 64)
    flash_mma<<<gridF, 128>>>(qh, kh, vh, ctx);

    gemm_mma<false><<<gridP, 256>>>(ctx, wo, out, nullptr, 1.0f);
}

// round 9
// speedup vs baseline: 6.5950x; 1.0310x over previous
#include <cuda_runtime.h>
#include <cuda_fp16.h>
#include <cstdint>

#define MDIM   1024
#define NHEADS 16
#define HDIM   64
#define BATCH  4
#define SEQ    2048
#define MROWS  (BATCH * SEQ)   // 8192

// 0.125 * log2(e): Q pre-scale so softmax can use ex2 directly
#define QSCALE 0.1803368801111191f

__device__ __align__(16) __half g_qh[BATCH * NHEADS * SEQ * HDIM];  // [B,H,S,dh] fp16
__device__ __align__(16) __half g_kh[BATCH * NHEADS * SEQ * HDIM];
__device__ __align__(16) __half g_vh[BATCH * NHEADS * SEQ * HDIM];
__device__ __align__(16) float  g_ctx[BATCH * SEQ * MDIM];          // [B,S,H*dh] fp32

// ---------------- helpers ----------------------------------------------------
__device__ __forceinline__ void mma16816(float* d, const uint32_t* a,
                                         const uint32_t* b) {
    asm volatile(
        "mma.sync.aligned.m16n8k16.row.col.f32.f16.f16.f32 "
        "{%0,%1,%2,%3}, {%4,%5,%6,%7}, {%8,%9}, {%0,%1,%2,%3};"
        : "+f"(d[0]), "+f"(d[1]), "+f"(d[2]), "+f"(d[3])
        : "r"(a[0]), "r"(a[1]), "r"(a[2]), "r"(a[3]),
          "r"(b[0]), "r"(b[1]));
}
__device__ __forceinline__ uint32_t f2h2(float x, float y) {
    __half2 h = __floats2half2_rn(x, y);
    return *(uint32_t*)&h;
}
__device__ __forceinline__ uint32_t smem_u32(const void* p) {
    uint32_t a;
    asm("{ .reg .u64 t; cvta.to.shared.u64 t, %1; cvt.u32.u64 %0, t; }"
        : "=r"(a) : "l"(p));
    return a;
}
__device__ __forceinline__ void ldmx4(uint32_t* r, uint32_t addr) {
    asm volatile("ldmatrix.sync.aligned.m8n8.x4.shared.b16 {%0,%1,%2,%3}, [%4];"
                 : "=r"(r[0]), "=r"(r[1]), "=r"(r[2]), "=r"(r[3]) : "r"(addr));
}
__device__ __forceinline__ void ldmx4t(uint32_t* r, uint32_t addr) {
    asm volatile("ldmatrix.sync.aligned.m8n8.x4.trans.shared.b16 {%0,%1,%2,%3}, [%4];"
                 : "=r"(r[0]), "=r"(r[1]), "=r"(r[2]), "=r"(r[3]) : "r"(addr));
}
__device__ __forceinline__ float ex2(float x) {
    float y;
    asm("ex2.approx.f32 %0, %1;" : "=f"(y) : "f"(x));
    return y;
}
#define CP_ASYNC16(dst, src) \
    asm volatile("cp.async.ca.shared.global [%0], [%1], 16;" \
                 :: "r"(dst), "l"(src) : "memory")
#define CP_COMMIT  asm volatile("cp.async.commit_group;" ::: "memory")
#define CP_WAIT0   asm volatile("cp.async.wait_group 0;" ::: "memory")
#define CP_WAIT1   asm volatile("cp.async.wait_group 1;" ::: "memory")

// ---------------- fp16 tensor-core GEMM --------------------------------------
// C = A(M,1024) * W(1024,1024)^T.  BM=BN=128, BK=32, 256 thr, 8 warps (2x4),
// warp tile 64x32. Double-buffered smem, ONE sync per k-tile, ldmatrix frags.
#define LDS_H 40

template<bool HEAD_OUT>
__global__ __launch_bounds__(256)
void gemm_mma(const float* __restrict__ A,
              const float* __restrict__ W,
              float* __restrict__ Cf,
              __half* __restrict__ Ch,
              float scale) {
    __shared__ __align__(16) __half As[2][128][LDS_H];
    __shared__ __align__(16) __half Ws[2][128][LDS_H];

    const int tid  = threadIdx.x;
    const int wid  = tid >> 5;
    const int lane = tid & 31;
    const int gid  = lane >> 2;
    const int tid4 = lane & 3;
    const int g    = lane >> 3;
    const int rl   = lane & 7;
    const int wm   = (wid >> 2) * 64;
    const int wn   = (wid & 3) * 32;
    const int bm   = blockIdx.y * 128;
    const int bn   = blockIdx.x * 128;

    const int lrow = tid >> 3;
    const int c4   = tid & 7;
    const float* gA = A + (size_t)(bm + lrow) * MDIM + c4 * 4;
    const float* gW = W + (size_t)(bn + lrow) * MDIM + c4 * 4;

    // ldmatrix lane addresses (bytes); row stride = LDS_H*2 = 80 B
    const uint32_t a_lo = (uint32_t)(((g & 1) * 8 + rl) * (LDS_H * 2) + (g >> 1) * 16);
    const uint32_t w_lo = (uint32_t)(((g >> 1) * 8 + rl) * (LDS_H * 2) + (g & 1) * 16);
    const uint32_t abase[2] = {
        smem_u32(&As[0][0][0]) + a_lo + (uint32_t)wm * (LDS_H * 2),
        smem_u32(&As[1][0][0]) + a_lo + (uint32_t)wm * (LDS_H * 2) };
    const uint32_t wbase[2] = {
        smem_u32(&Ws[0][0][0]) + w_lo + (uint32_t)wn * (LDS_H * 2),
        smem_u32(&Ws[1][0][0]) + w_lo + (uint32_t)wn * (LDS_H * 2) };

    float4 ra[4], rw[4];

    #define LDG_STAGE(kt) do {                                                 \
        const int _k0 = (kt) * 32;                                             \
        _Pragma("unroll")                                                      \
        for (int j = 0; j < 4; j++) {                                          \
            ra[j] = *(const float4*)(gA + (size_t)(j * 32) * MDIM + _k0);      \
            rw[j] = *(const float4*)(gW + (size_t)(j * 32) * MDIM + _k0);      \
        }                                                                      \
    } while (0)

    #define STS_STAGE(s) do {                                                  \
        _Pragma("unroll")                                                      \
        for (int j = 0; j < 4; j++) {                                          \
            uint2 av = { f2h2(ra[j].x, ra[j].y), f2h2(ra[j].z, ra[j].w) };     \
            uint2 wv = { f2h2(rw[j].x, rw[j].y), f2h2(rw[j].z, rw[j].w) };     \
            *(uint2*)&As[s][lrow + j * 32][c4 * 4] = av;                       \
            *(uint2*)&Ws[s][lrow + j * 32][c4 * 4] = wv;                       \
        }                                                                      \
    } while (0)

    float acc[4][4][4] = {};

    LDG_STAGE(0);
    STS_STAGE(0);
    __syncthreads();

    for (int kt = 0; kt < 32; kt++) {
        const int cur = kt & 1;
        if (kt + 1 < 32) LDG_STAGE(kt + 1);

        #pragma unroll
        for (int ks = 0; ks < 2; ks++) {
            uint32_t af[4][4], bf[8];
            #pragma unroll
            for (int i = 0; i < 4; i++)
                ldmx4(af[i], abase[cur] + (uint32_t)(i * 16 * (LDS_H * 2) + ks * 32));
            ldmx4(bf,     wbase[cur] + (uint32_t)(ks * 32));
            ldmx4(bf + 4, wbase[cur] + (uint32_t)(16 * (LDS_H * 2) + ks * 32));
            #pragma unroll
            for (int i = 0; i < 4; i++)
                #pragma unroll
                for (int j = 0; j < 4; j++)
                    mma16816(acc[i][j], af[i], bf + j * 2);
        }

        if (kt + 1 < 32) STS_STAGE(cur ^ 1);   // other buffer: safe pre-sync
        __syncthreads();
    }

    #pragma unroll
    for (int i = 0; i < 4; i++) {
        #pragma unroll
        for (int j = 0; j < 4; j++) {
            const int n = bn + wn + j * 8 + 2 * tid4;
            #pragma unroll
            for (int half_ = 0; half_ < 2; half_++) {
                const int m = bm + wm + i * 16 + gid + half_ * 8;
                float vx = acc[i][j][half_ * 2];
                float vy = acc[i][j][half_ * 2 + 1];
                if (HEAD_OUT) {
                    const int bb = m >> 11, ss = m & 2047;
                    const int hh = n >> 6,  dd = n & 63;
                    uint32_t hv = f2h2(vx * scale, vy * scale);
                    *(uint32_t*)&Ch[(((size_t)(bb * NHEADS + hh) * SEQ) + ss) * HDIM + dd] = hv;
                } else {
                    float2 v = { vx, vy };
                    *(float2*)&Cf[(size_t)m * MDIM + n] = v;
                }
            }
        }
    }
}

// ---------------- tensor-core flash attention ---------------------------------
// 128 threads / 4 warps; Q-tile 128x64 (2 m16 A-tiles per warp); 32 key-tiles.
// K AND V row-major via cp.async; B-frags via ldmatrix / ldmatrix.trans.
// Softmax in log2 domain (Q pre-scaled by 0.125*log2e), exp via ex2.approx.
#define FH 72

__global__ __launch_bounds__(128)
void flash_mma(const __half* __restrict__ qh,
               const __half* __restrict__ kh,
               const __half* __restrict__ vh,
               float* __restrict__ ctx) {
    __shared__ __align__(16) __half Ks[2][64][FH];
    __shared__ __align__(16) __half Vs[2][64][FH];

    const int tid  = threadIdx.x;
    const int wid  = tid >> 5;
    const int lane = tid & 31;
    const int gid  = lane >> 2;
    const int tid4 = lane & 3;

    const int bh = blockIdx.y;
    const int b  = bh >> 4;
    const int h  = bh & 15;
    const int q0 = blockIdx.x * 128;

    const __half* qb = qh + (size_t)bh * SEQ * HDIM;
    const __half* kb = kh + (size_t)bh * SEQ * HDIM;
    const __half* vb = vh + (size_t)bh * SEQ * HDIM;

    const int key   = tid & 63;
    const int dbase = (tid >> 6) * 32;
    const uint32_t ksm[2] = { smem_u32(&Ks[0][key][dbase]), smem_u32(&Ks[1][key][dbase]) };
    const uint32_t vsm[2] = { smem_u32(&Vs[0][key][dbase]), smem_u32(&Vs[1][key][dbase]) };

    #define CPKV(t, s) do {                                                     \
        const __half* _ks = kb + ((size_t)(t) * 64 + key) * HDIM + dbase;       \
        const __half* _vs = vb + ((size_t)(t) * 64 + key) * HDIM + dbase;       \
        _Pragma("unroll")                                                       \
        for (int i = 0; i < 4; i++) {                                           \
            CP_ASYNC16(ksm[s] + 16 * i, _ks + 8 * i);                           \
            CP_ASYNC16(vsm[s] + 16 * i, _vs + 8 * i);                           \
        }                                                                       \
    } while (0)

    const int g  = lane >> 3;
    const int rl = lane & 7;
    const uint32_t koff = (uint32_t)(((g >> 1) * 8 + rl) * FH + 8 * (g & 1)) * 2u;
    const uint32_t voff = (uint32_t)((8 * (g & 1) + rl) * FH + 8 * (g >> 1)) * 2u;
    const uint32_t kbase[2] = { smem_u32(&Ks[0][0][0]) + koff, smem_u32(&Ks[1][0][0]) + koff };
    const uint32_t vbase[2] = { smem_u32(&Vs[0][0][0]) + voff, smem_u32(&Vs[1][0][0]) + voff };

    // ---- Q fragments straight from gmem ----
    uint32_t aq[2][4][4];
    {
        const __half* qrow = qb + (size_t)q0 * HDIM;
        #pragma unroll
        for (int ia = 0; ia < 2; ia++) {
            const int r = wid * 32 + ia * 16 + gid;
            #pragma unroll
            for (int ks = 0; ks < 4; ks++) {
                const int kc = 16 * ks + 2 * tid4;
                aq[ia][ks][0] = *(const uint32_t*)(qrow + (size_t)r * HDIM + kc);
                aq[ia][ks][1] = *(const uint32_t*)(qrow + (size_t)(r + 8) * HDIM + kc);
                aq[ia][ks][2] = *(const uint32_t*)(qrow + (size_t)r * HDIM + kc + 8);
                aq[ia][ks][3] = *(const uint32_t*)(qrow + (size_t)(r + 8) * HDIM + kc + 8);
            }
        }
    }

    float m[2][2], l[2][2];
    #pragma unroll
    for (int ia = 0; ia < 2; ia++) {
        m[ia][0] = -1e30f; m[ia][1] = -1e30f;
        l[ia][0] = 0.f;    l[ia][1] = 0.f;
    }
    float oacc[2][8][4] = {};

    CPKV(0, 0); CP_COMMIT;
    CPKV(1, 1); CP_COMMIT;
    CP_WAIT1;
    __syncthreads();

    for (int t = 0; t < 32; t++) {
        const int s = t & 1;

        // ---- S = Q K^T (log2-scaled scores) ----
        float sacc[2][8][4] = {};
        #pragma unroll
        for (int ks = 0; ks < 4; ks++) {
            #pragma unroll
            for (int jp = 0; jp < 4; jp++) {
                uint32_t bf[4];
                ldmx4(bf, kbase[s] + (uint32_t)(2 * jp * 8 * FH + 16 * ks) * 2u);
                mma16816(sacc[0][2 * jp],     aq[0][ks], bf);
                mma16816(sacc[1][2 * jp],     aq[1][ks], bf);
                mma16816(sacc[0][2 * jp + 1], aq[0][ks], bf + 2);
                mma16816(sacc[1][2 * jp + 1], aq[1][ks], bf + 2);
            }
        }

        // ---- online softmax (base-2) + P repack ----
        uint32_t ap[2][4][4];
        #pragma unroll
        for (int ia = 0; ia < 2; ia++) {
            float mx0 = -1e30f, mx1 = -1e30f;
            #pragma unroll
            for (int j = 0; j < 8; j++) {
                mx0 = fmaxf(mx0, fmaxf(sacc[ia][j][0], sacc[ia][j][1]));
                mx1 = fmaxf(mx1, fmaxf(sacc[ia][j][2], sacc[ia][j][3]));
            }
            #pragma unroll
            for (int off = 1; off <= 2; off <<= 1) {
                mx0 = fmaxf(mx0, __shfl_xor_sync(0xffffffffu, mx0, off));
                mx1 = fmaxf(mx1, __shfl_xor_sync(0xffffffffu, mx1, off));
            }
            const float mn0 = fmaxf(m[ia][0], mx0);
            const float mn1 = fmaxf(m[ia][1], mx1);
            const float sc0 = ex2(m[ia][0] - mn0);
            const float sc1 = ex2(m[ia][1] - mn1);

            float rs0 = 0.f, rs1 = 0.f;
            #pragma unroll
            for (int j = 0; j < 8; j++) {
                sacc[ia][j][0] = ex2(sacc[ia][j][0] - mn0);
                sacc[ia][j][1] = ex2(sacc[ia][j][1] - mn0);
                sacc[ia][j][2] = ex2(sacc[ia][j][2] - mn1);
                sacc[ia][j][3] = ex2(sacc[ia][j][3] - mn1);
                rs0 += sacc[ia][j][0] + sacc[ia][j][1];
                rs1 += sacc[ia][j][2] + sacc[ia][j][3];
            }
            #pragma unroll
            for (int off = 1; off <= 2; off <<= 1) {
                rs0 += __shfl_xor_sync(0xffffffffu, rs0, off);
                rs1 += __shfl_xor_sync(0xffffffffu, rs1, off);
            }
            l[ia][0] = l[ia][0] * sc0 + rs0;  m[ia][0] = mn0;
            l[ia][1] = l[ia][1] * sc1 + rs1;  m[ia][1] = mn1;

            #pragma unroll
            for (int j = 0; j < 8; j++) {
                oacc[ia][j][0] *= sc0;  oacc[ia][j][1] *= sc0;
                oacc[ia][j][2] *= sc1;  oacc[ia][j][3] *= sc1;
            }
            #pragma unroll
            for (int ks = 0; ks < 4; ks++) {
                ap[ia][ks][0] = f2h2(sacc[ia][2 * ks][0],     sacc[ia][2 * ks][1]);
                ap[ia][ks][1] = f2h2(sacc[ia][2 * ks][2],     sacc[ia][2 * ks][3]);
                ap[ia][ks][2] = f2h2(sacc[ia][2 * ks + 1][0], sacc[ia][2 * ks + 1][1]);
                ap[ia][ks][3] = f2h2(sacc[ia][2 * ks + 1][2], sacc[ia][2 * ks + 1][3]);
            }
        }

        // ---- O += P V ----
        #pragma unroll
        for (int ks = 0; ks < 4; ks++) {
            #pragma unroll
            for (int jp = 0; jp < 4; jp++) {
                uint32_t bf[4];
                ldmx4t(bf, vbase[s] + (uint32_t)(16 * ks * FH + 2 * jp * 8) * 2u);
                mma16816(oacc[0][2 * jp],     ap[0][ks], bf);
                mma16816(oacc[1][2 * jp],     ap[1][ks], bf);
                mma16816(oacc[0][2 * jp + 1], ap[0][ks], bf + 2);
                mma16816(oacc[1][2 * jp + 1], ap[1][ks], bf + 2);
            }
        }

        CP_WAIT0;
        __syncthreads();
        if (t + 2 < 32) {
            CPKV(t + 2, s); CP_COMMIT;
        }
    }

    // ---- normalize + write ctx ----
    #pragma unroll
    for (int ia = 0; ia < 2; ia++) {
        const int r = q0 + wid * 32 + ia * 16 + gid;
        const float inv0 = 1.f / l[ia][0];
        const float inv1 = 1.f / l[ia][1];
        #pragma unroll
        for (int j = 0; j < 8; j++) {
            const int d = h * HDIM + 8 * j + 2 * tid4;
            float2 v0 = { oacc[ia][j][0] * inv0, oacc[ia][j][1] * inv0 };
            float2 v1 = { oacc[ia][j][2] * inv1, oacc[ia][j][3] * inv1 };
            *(float2*)&ctx[((size_t)(b * SEQ + r))     * MDIM + d] = v0;
            *(float2*)&ctx[((size_t)(b * SEQ + r + 8)) * MDIM + d] = v1;
        }
    }
}

// ---------------- launch -------------------------------------------------------
extern "C" void kernel_launch(void* const* d_in, const int* in_sizes, int n_in,
                              void* d_out, int out_size) {
    const float* q  = (const float*)d_in[0];
    const float* k  = (const float*)d_in[1];
    const float* v  = (const float*)d_in[2];
    const float* wq = (const float*)d_in[3];
    const float* wk = (const float*)d_in[4];
    const float* wv = (const float*)d_in[5];
    const float* wo = (const float*)d_in[6];
    float* out = (float*)d_out;

    __half *qh, *kh, *vh;
    float *ctx;
    cudaGetSymbolAddress((void**)&qh,  g_qh);
    cudaGetSymbolAddress((void**)&kh,  g_kh);
    cudaGetSymbolAddress((void**)&vh,  g_vh);
    cudaGetSymbolAddress((void**)&ctx, g_ctx);

    dim3 gridP(MDIM / 128, MROWS / 128);   // (8, 64)
    gemm_mma<true ><<<gridP, 256>>>(q, wq, nullptr, qh, QSCALE);
    gemm_mma<true ><<<gridP, 256>>>(k, wk, nullptr, kh, 1.0f);
    gemm_mma<true ><<<gridP, 256>>>(v, wv, nullptr, vh, 1.0f);

    dim3 gridF(SEQ / 128, BATCH * NHEADS); // (16, 64)
    flash_mma<<<gridF, 128>>>(qh, kh, vh, ctx);

    gemm_mma<false><<<gridP, 256>>>(ctx, wo, out, nullptr, 1.0f);
}